// round 5
// baseline (speedup 1.0000x reference)
#include <cuda_runtime.h>
#include <math.h>
#include <stdint.h>

// Problem constants
constexpr int Bb = 2;
constexpr int Ss = 2048;
constexpr int Dd = 768;
constexpr int Hh = 12;
constexpr int DHd = 64;
constexpr int WIN = 128;

// Scratch (device globals; no allocation allowed)
__device__ float g_Q[Bb * Ss * Hh * DHd];
__device__ float g_K[Bb * Ss * Hh * DHd];
__device__ float g_V[Bb * Ss * Hh * DHd];
__device__ float g_Z[Bb * Ss * Hh * DHd];

using ull = unsigned long long;

__device__ __forceinline__ uint32_t f2tf32(float x) {
    uint32_t u;
    asm("cvt.rna.tf32.f32 %0, %1;" : "=r"(u) : "f"(x));
    return u;
}
__device__ __forceinline__ ull pack2(float x, float y) {
    ull r;
    asm("mov.b64 %0, {%1, %2};" : "=l"(r) : "f"(x), "f"(y));
    return r;
}
__device__ __forceinline__ void unpack2(ull v, float& x, float& y) {
    asm("mov.b64 {%0, %1}, %2;" : "=f"(x), "=f"(y) : "l"(v));
}
__device__ __forceinline__ void ffma2(ull& d, ull a, ull b) {
    asm("fma.rn.f32x2 %0, %1, %2, %0;" : "+l"(d) : "l"(a), "l"(b));
}

// ---------------------------------------------------------------------------
// tf32 tensor-core GEMM, fragment-major smem, 2-stage pipeline.
// C[M,N] = A[M,K]*B[K,N] + bias[N].  BM=128, BN=64, BK=32, 256 thr, 8 warps.
// Fragment-major layouts (per stage, float offsets):
//   A: aoff(kk,mb,lane,frag) = kk*1028 + mb*128 + lane*4 + frag
//      per-kk extent 1024 <= stride 1028; stage size SA = 4112.
//   B: boff(kk,nb,lane,frag) = kk*560 + nb*70 + lane*2 + frag
//      per-kk extent 554 <= stride 560;  stage size SB = 2240.
// Consumer: A frag = 1 LDS.128, B frag = 1 LDS.64, conflict-free.
// blockIdx.z selects one of up to 3 problem instances (QKV fused).
// ---------------------------------------------------------------------------
constexpr int SA = 4112;   // A stage size (floats)
constexpr int SB = 2240;   // B stage size (floats)  [bugfix: was 2112 w/ 514 kk stride]
constexpr int GEMM_SMEM = (2 * SA + 2 * SB) * 4;   // 50816 bytes

template <bool HEADB>
__global__ __launch_bounds__(256, 2) void tgemm_k(
    const float* __restrict__ A0, const float* __restrict__ A1, const float* __restrict__ A2,
    const float* __restrict__ Bm0, const float* __restrict__ Bm1, const float* __restrict__ Bm2,
    const float* __restrict__ bias0, const float* __restrict__ bias1, const float* __restrict__ bias2,
    float* __restrict__ C0, float* __restrict__ C1, float* __restrict__ C2,
    int M, int N, int K)
{
    extern __shared__ uint32_t smem_u[];
    uint32_t* Abuf = smem_u;            // 2 * SA
    uint32_t* Bbuf = smem_u + 2 * SA;   // 2 * SB

    const int z = blockIdx.z;
    const float* A    = (z == 0) ? A0    : (z == 1) ? A1    : A2;
    const float* Bm   = (z == 0) ? Bm0   : (z == 1) ? Bm1   : Bm2;
    const float* bias = (z == 0) ? bias0 : (z == 1) ? bias1 : bias2;
    float*       C    = (z == 0) ? C0    : (z == 1) ? C1    : C2;

    const int t  = threadIdx.x;
    const int m0 = blockIdx.y * 128;
    const int n0 = blockIdx.x * 64;

    const float* bbase;
    int ldb;
    if (HEADB) { bbase = Bm + (size_t)(n0 >> 6) * K * 64; ldb = 64; }
    else       { bbase = Bm + n0;                          ldb = N;  }

    const int warp  = t >> 5;
    const int lane  = t & 31;
    const int wm    = (warp >> 1) * 32;
    const int wn    = (warp & 1) * 32;

    // loader addressing
    const int ar  = t >> 3;          // A row base (0..31), rows ar + i*32
    const int ac4 = (t & 7) * 4;     // A col base (0..28)
    const int br  = t >> 4;          // B row base (0..15), rows br + i*16
    const int bc4 = (t & 15) * 4;    // B col base (0..60)

    // precomputed A-store constants (same for all i)
    const int a_kk    = ac4 >> 3;
    const int a_khalf = (ac4 >> 2) & 1;

    float4 ra[4];
    float4 rb[2];

    auto ldg = [&](int k0) {
#pragma unroll
        for (int i = 0; i < 4; i++)
            ra[i] = *(const float4*)&A[(size_t)(m0 + ar + i * 32) * K + k0 + ac4];
#pragma unroll
        for (int i = 0; i < 2; i++)
            rb[i] = *(const float4*)&bbase[(size_t)(k0 + br + i * 16) * ldb + bc4];
    };

    auto sts = [&](int st) {
        // A: value (row r, col k=ac4+j) -> frag-major
        uint32_t* Ab = Abuf + st * SA + a_kk * 1028;
#pragma unroll
        for (int i = 0; i < 4; i++) {
            int r  = ar + i * 32;
            int mb = r >> 4;
            int grp = r & 7;
            int rowhalf = (r >> 3) & 1;
            int frag = rowhalf + 2 * a_khalf;
            uint32_t* p = Ab + mb * 128 + grp * 16 + frag;
            float v[4] = {ra[i].x, ra[i].y, ra[i].z, ra[i].w};
#pragma unroll
            for (int j = 0; j < 4; j++)
                p[j * 4] = f2tf32(v[j]);
        }
        // B: value (row k, col bc4+j) -> frag-major
#pragma unroll
        for (int i = 0; i < 2; i++) {
            int k    = br + i * 16;
            int kk   = k >> 3;
            int frag = (k >> 2) & 1;
            int tig  = k & 3;
            uint32_t* p = Bbuf + st * SB + kk * 560 + frag + tig * 2;
            float v[4] = {rb[i].x, rb[i].y, rb[i].z, rb[i].w};
#pragma unroll
            for (int j = 0; j < 4; j++) {
                int col = bc4 + j;
                p[(col >> 3) * 70 + (col & 7) * 8] = f2tf32(v[j]);
            }
        }
    };

    float acc[2][4][4];
#pragma unroll
    for (int mt = 0; mt < 2; mt++)
#pragma unroll
        for (int nt = 0; nt < 4; nt++)
#pragma unroll
            for (int j = 0; j < 4; j++) acc[mt][nt][j] = 0.0f;

    ldg(0);
    sts(0);
    __syncthreads();

    int cur = 0;
    for (int k0 = 0; k0 < K; k0 += 32) {
        const bool notlast = (k0 + 32 < K);
        if (notlast) ldg(k0 + 32);

        const uint32_t* As = Abuf + cur * SA;
        const uint32_t* Bs = Bbuf + cur * SB;

#pragma unroll
        for (int kk = 0; kk < 4; kk++) {
            uint4 a4[2];
            uint2 b2[4];
#pragma unroll
            for (int mt = 0; mt < 2; mt++) {
                int mb = (wm + mt * 16) >> 4;
                a4[mt] = *(const uint4*)&As[kk * 1028 + mb * 128 + lane * 4];
            }
#pragma unroll
            for (int nt = 0; nt < 4; nt++) {
                int nb = (wn >> 3) + nt;
                b2[nt] = *(const uint2*)&Bs[kk * 560 + nb * 70 + lane * 2];
            }
#pragma unroll
            for (int mt = 0; mt < 2; mt++)
#pragma unroll
                for (int nt = 0; nt < 4; nt++) {
                    asm volatile(
                        "mma.sync.aligned.m16n8k8.row.col.f32.tf32.tf32.f32 "
                        "{%0,%1,%2,%3}, {%4,%5,%6,%7}, {%8,%9}, {%0,%1,%2,%3};\n"
                        : "+f"(acc[mt][nt][0]), "+f"(acc[mt][nt][1]),
                          "+f"(acc[mt][nt][2]), "+f"(acc[mt][nt][3])
                        : "r"(a4[mt].x), "r"(a4[mt].y), "r"(a4[mt].z), "r"(a4[mt].w),
                          "r"(b2[nt].x), "r"(b2[nt].y));
                }
        }

        if (notlast) sts(cur ^ 1);
        __syncthreads();
        cur ^= 1;
    }

    const int group = lane >> 2;
    const int tig   = lane & 3;
#pragma unroll
    for (int mt = 0; mt < 2; mt++) {
#pragma unroll
        for (int nt = 0; nt < 4; nt++) {
            int col  = n0 + wn + nt * 8 + tig * 2;
            float bx = bias[col];
            float by = bias[col + 1];
            int r0 = m0 + wm + mt * 16 + group;
            float2 o0 = make_float2(acc[mt][nt][0] + bx, acc[mt][nt][1] + by);
            float2 o1 = make_float2(acc[mt][nt][2] + bx, acc[mt][nt][3] + by);
            *(float2*)&C[(size_t)r0 * N + col]       = o0;
            *(float2*)&C[(size_t)(r0 + 8) * N + col] = o1;
        }
    }
}

// ---------------------------------------------------------------------------
// Rotary (full head, ROT == DH == 64). Pair (i, i+32) shares angle pos/freq[i].
// ---------------------------------------------------------------------------
__global__ __launch_bounds__(256) void rotary_k(float* __restrict__ Q,
                                                float* __restrict__ K)
{
    const int total_half = Bb * Ss * Hh * 32;
    int tid = blockIdx.x * blockDim.x + threadIdx.x;
    if (tid >= 2 * total_half) return;

    float* buf = (tid < total_half) ? Q : K;
    int id  = (tid < total_half) ? tid : tid - total_half;
    int i   = id & 31;
    int bsh = id >> 5;
    int s   = (bsh / Hh) % Ss;

    float inv_freq = expf(-(float)(2 * i) * (1.0f / 64.0f) * 9.210340371976184f);
    float ang = (float)s * inv_freq;
    float sn, cs;
    sincosf(ang, &sn, &cs);

    size_t base = (size_t)bsh * 64;
    float x = buf[base + i];
    float y = buf[base + i + 32];
    buf[base + i]      = x * cs - y * sn;
    buf[base + i + 32] = y * cs + x * sn;
}

// ---------------------------------------------------------------------------
// Sliding-window attention with packed f32x2 FFMA.
// ---------------------------------------------------------------------------
constexpr int QP  = 65;
constexpr int KP  = 65;
constexpr int VP  = 68;
constexpr int SCP = 196;

__global__ __launch_bounds__(256) void attn_k(
    const float* __restrict__ Q, const float* __restrict__ K,
    const float* __restrict__ V, float* __restrict__ Z)
{
    extern __shared__ float sm[];
    float* Qs  = sm;
    float* KVs = sm + 64 * QP;
    float* Sc  = sm + 64 * QP + 64 * VP;

    const int t  = threadIdx.x;
    const int q0 = blockIdx.x * 64;
    const int h  = blockIdx.y;
    const int b  = blockIdx.z;

    const int ty4 = (t >> 4) * 4;
    const int tx4 = (t & 15) * 4;

#pragma unroll
    for (int i = 0; i < 4; i++) {
        int idx = t + i * 256;
        int r = idx >> 4;
        int c = (idx & 15) * 4;
        float4 v = *(const float4*)&Q[(((size_t)(b * Ss + q0 + r)) * Hh + h) * 64 + c];
        Qs[r * QP + c + 0] = v.x;
        Qs[r * QP + c + 1] = v.y;
        Qs[r * QP + c + 2] = v.z;
        Qs[r * QP + c + 3] = v.w;
    }

    for (int c = 0; c < 3; c++) {
        const int j0 = q0 - 128 + c * 64;
        __syncthreads();
#pragma unroll
        for (int i = 0; i < 4; i++) {
            int idx = t + i * 256;
            int r = idx >> 4;
            int cc = (idx & 15) * 4;
            int jg = j0 + r;
            float4 v = make_float4(0.f, 0.f, 0.f, 0.f);
            if (jg >= 0)
                v = *(const float4*)&K[(((size_t)(b * Ss + jg)) * Hh + h) * 64 + cc];
            KVs[r * KP + cc + 0] = v.x;
            KVs[r * KP + cc + 1] = v.y;
            KVs[r * KP + cc + 2] = v.z;
            KVs[r * KP + cc + 3] = v.w;
        }
        __syncthreads();

        ull accp[4][2];
#pragma unroll
        for (int i = 0; i < 4; i++) { accp[i][0] = 0ull; accp[i][1] = 0ull; }

#pragma unroll 4
        for (int d = 0; d < 64; d++) {
            float k0v = KVs[(tx4 + 0) * KP + d];
            float k1v = KVs[(tx4 + 1) * KP + d];
            float k2v = KVs[(tx4 + 2) * KP + d];
            float k3v = KVs[(tx4 + 3) * KP + d];
            ull kb0 = pack2(k0v, k1v);
            ull kb1 = pack2(k2v, k3v);
#pragma unroll
            for (int i = 0; i < 4; i++) {
                float av = Qs[(ty4 + i) * QP + d];
                ull ab = pack2(av, av);
                ffma2(accp[i][0], ab, kb0);
                ffma2(accp[i][1], ab, kb1);
            }
        }

#pragma unroll
        for (int i = 0; i < 4; i++) {
            float s0, s1, s2, s3;
            unpack2(accp[i][0], s0, s1);
            unpack2(accp[i][1], s2, s3);
            float sv[4] = {s0, s1, s2, s3};
            int qg = q0 + ty4 + i;
#pragma unroll
            for (int j = 0; j < 4; j++) {
                int jg = j0 + tx4 + j;
                bool ok = (jg >= 0) && (jg <= qg) && (jg > qg - WIN);
                Sc[(ty4 + i) * SCP + c * 64 + tx4 + j] = ok ? sv[j] * 0.125f : -1e30f;
            }
        }
    }
    __syncthreads();

    {
        int r = t >> 2;
        int p = t & 3;
        float mx = -1e30f;
        for (int jj = p * 48; jj < p * 48 + 48; jj++)
            mx = fmaxf(mx, Sc[r * SCP + jj]);
        mx = fmaxf(mx, __shfl_xor_sync(0xFFFFFFFFu, mx, 1));
        mx = fmaxf(mx, __shfl_xor_sync(0xFFFFFFFFu, mx, 2));
        float sum = 0.0f;
        for (int jj = p * 48; jj < p * 48 + 48; jj++) {
            float e = __expf(Sc[r * SCP + jj] - mx);
            Sc[r * SCP + jj] = e;
            sum += e;
        }
        sum += __shfl_xor_sync(0xFFFFFFFFu, sum, 1);
        sum += __shfl_xor_sync(0xFFFFFFFFu, sum, 2);
        float inv = 1.0f / sum;
        for (int jj = p * 48; jj < p * 48 + 48; jj++)
            Sc[r * SCP + jj] *= inv;
    }

    ull op[4][2];
#pragma unroll
    for (int i = 0; i < 4; i++) { op[i][0] = 0ull; op[i][1] = 0ull; }

    for (int c = 0; c < 3; c++) {
        const int j0 = q0 - 128 + c * 64;
        __syncthreads();
#pragma unroll
        for (int i = 0; i < 4; i++) {
            int idx = t + i * 256;
            int r = idx >> 4;
            int cc = (idx & 15) * 4;
            int jg = j0 + r;
            float4 v = make_float4(0.f, 0.f, 0.f, 0.f);
            if (jg >= 0)
                v = *(const float4*)&V[(((size_t)(b * Ss + jg)) * Hh + h) * 64 + cc];
            *(float4*)&KVs[r * VP + cc] = v;
        }
        __syncthreads();

#pragma unroll 4
        for (int jj = 0; jj < 64; jj++) {
            ulonglong2 vb = *(const ulonglong2*)&KVs[jj * VP + tx4];
#pragma unroll
            for (int i = 0; i < 4; i++) {
                float pv = Sc[(ty4 + i) * SCP + c * 64 + jj];
                ull pb = pack2(pv, pv);
                ffma2(op[i][0], pb, vb.x);
                ffma2(op[i][1], pb, vb.y);
            }
        }
    }

#pragma unroll
    for (int i = 0; i < 4; i++) {
        float4 o;
        unpack2(op[i][0], o.x, o.y);
        unpack2(op[i][1], o.z, o.w);
        *(float4*)&Z[(((size_t)(b * Ss + q0 + ty4 + i)) * Hh + h) * 64 + tx4] = o;
    }
}

// ---------------------------------------------------------------------------
extern "C" void kernel_launch(void* const* d_in, const int* in_sizes, int n_in,
                              void* d_out, int out_size)
{
    const float* qin = (const float*)d_in[0];
    const float* kin = (const float*)d_in[1];
    const float* vin = (const float*)d_in[2];
    const float* WQ  = (const float*)d_in[3];
    const float* WK  = (const float*)d_in[4];
    const float* WV  = (const float*)d_in[5];
    const float* WO  = (const float*)d_in[6];
    const float* bQ  = (const float*)d_in[7];
    const float* bK  = (const float*)d_in[8];
    const float* bV  = (const float*)d_in[9];
    const float* bO  = (const float*)d_in[10];
    float* out = (float*)d_out;

    float *pQ, *pK, *pV, *pZ;
    cudaGetSymbolAddress((void**)&pQ, g_Q);
    cudaGetSymbolAddress((void**)&pK, g_K);
    cudaGetSymbolAddress((void**)&pV, g_V);
    cudaGetSymbolAddress((void**)&pZ, g_Z);

    const int M = Bb * Ss;       // 4096
    const int N = Hh * DHd;      // 768
    const int Kd = Dd;           // 768

    size_t asmem = (size_t)(64 * QP + 64 * VP + 64 * SCP) * sizeof(float);
    cudaFuncSetAttribute(tgemm_k<true>,
                         cudaFuncAttributeMaxDynamicSharedMemorySize, GEMM_SMEM);
    cudaFuncSetAttribute(tgemm_k<false>,
                         cudaFuncAttributeMaxDynamicSharedMemorySize, GEMM_SMEM);
    cudaFuncSetAttribute(attn_k,
                         cudaFuncAttributeMaxDynamicSharedMemorySize, (int)asmem);

    // Fused QKV projections (z selects instance)
    tgemm_k<true><<<dim3(N / 64, M / 128, 3), 256, GEMM_SMEM>>>(
        qin, kin, vin, WQ, WK, WV, bQ, bK, bV, pQ, pK, pV, M, N, Kd);

    int rot_threads = 2 * Bb * Ss * Hh * 32;
    rotary_k<<<rot_threads / 256, 256>>>(pQ, pK);

    attn_k<<<dim3(Ss / 64, Hh, Bb), 256, asmem>>>(pQ, pK, pV, pZ);

    // Output projection
    tgemm_k<false><<<dim3(N / 64, M / 128, 1), 256, GEMM_SMEM>>>(
        pZ, pZ, pZ, WO, WO, WO, bO, bO, bO, out, out, out, M, N, Kd);
}

// round 7
// speedup vs baseline: 1.1434x; 1.1434x over previous
#include <cuda_runtime.h>
#include <math.h>
#include <stdint.h>

// Problem constants
constexpr int Bb = 2;
constexpr int Ss = 2048;
constexpr int Dd = 768;
constexpr int Hh = 12;
constexpr int DHd = 64;
constexpr int WIN = 128;

// Scratch (device globals; no allocation allowed)
__device__ __align__(16) float g_Q[Bb * Ss * Hh * DHd];
__device__ __align__(16) float g_K[Bb * Ss * Hh * DHd];
__device__ __align__(16) float g_V[Bb * Ss * Hh * DHd];
__device__ __align__(16) float g_Z[Bb * Ss * Hh * DHd];
// tf32-pre-rounded operands
__device__ __align__(16) float g_Aq[Bb * Ss * Dd];
__device__ __align__(16) float g_Ak[Bb * Ss * Dd];
__device__ __align__(16) float g_Av[Bb * Ss * Dd];
__device__ __align__(16) float g_Wq[Hh * Dd * DHd];
__device__ __align__(16) float g_Wk[Hh * Dd * DHd];
__device__ __align__(16) float g_Wv[Hh * Dd * DHd];
__device__ __align__(16) float g_Wo[Hh * DHd * Dd];

using ull = unsigned long long;

__device__ __forceinline__ uint32_t f2tf32(float x) {
    uint32_t u;
    asm("cvt.rna.tf32.f32 %0, %1;" : "=r"(u) : "f"(x));
    return u;
}
__device__ __forceinline__ float round_tf32(float x) {
    return __uint_as_float(f2tf32(x));
}
__device__ __forceinline__ ull pack2(float x, float y) {
    ull r;
    asm("mov.b64 %0, {%1, %2};" : "=l"(r) : "f"(x), "f"(y));
    return r;
}
__device__ __forceinline__ void unpack2(ull v, float& x, float& y) {
    asm("mov.b64 {%0, %1}, %2;" : "=f"(x), "=f"(y) : "l"(v));
}
__device__ __forceinline__ void ffma2(ull& d, ull a, ull b) {
    asm("fma.rn.f32x2 %0, %1, %2, %0;" : "+l"(d) : "l"(a), "l"(b));
}
__device__ __forceinline__ void cpa16(uint32_t dst, const void* src) {
    asm volatile("cp.async.cg.shared.global [%0], [%1], 16;"
                 :: "r"(dst), "l"(src) : "memory");
}
#define CP_COMMIT() asm volatile("cp.async.commit_group;" ::: "memory")
#define CP_WAIT1()  asm volatile("cp.async.wait_group 1;" ::: "memory")

// ---------------------------------------------------------------------------
// Pre-rounding kernels: copy with cvt.rna.tf32 per element.
// ---------------------------------------------------------------------------
__global__ __launch_bounds__(256) void round3_k(
    const float* __restrict__ a, const float* __restrict__ b,
    const float* __restrict__ c,
    float* __restrict__ da, float* __restrict__ db, float* __restrict__ dc)
{
    int idx = blockIdx.x * 256 + threadIdx.x;   // float4 index
    const float* s = (blockIdx.y == 0) ? a : (blockIdx.y == 1) ? b : c;
    float*       d = (blockIdx.y == 0) ? da : (blockIdx.y == 1) ? db : dc;
    float4 v = ((const float4*)s)[idx];
    v.x = round_tf32(v.x); v.y = round_tf32(v.y);
    v.z = round_tf32(v.z); v.w = round_tf32(v.w);
    ((float4*)d)[idx] = v;
}
__global__ __launch_bounds__(256) void round4_k(
    const float* __restrict__ a, const float* __restrict__ b,
    const float* __restrict__ c, const float* __restrict__ e,
    float* __restrict__ da, float* __restrict__ db,
    float* __restrict__ dc, float* __restrict__ de)
{
    int idx = blockIdx.x * 256 + threadIdx.x;
    const float* s = (blockIdx.y == 0) ? a : (blockIdx.y == 1) ? b
                   : (blockIdx.y == 2) ? c : e;
    float*       d = (blockIdx.y == 0) ? da : (blockIdx.y == 1) ? db
                   : (blockIdx.y == 2) ? dc : de;
    float4 v = ((const float4*)s)[idx];
    v.x = round_tf32(v.x); v.y = round_tf32(v.y);
    v.z = round_tf32(v.z); v.w = round_tf32(v.w);
    ((float4*)d)[idx] = v;
}

// ---------------------------------------------------------------------------
// tf32 mma GEMM, cp.async 3-stage, BM=128 BN=128 BK=32, 256 thr = 8 warps.
// Warp tile 64x32 (2 warps in m x 4 in n). Inputs PRE-ROUNDED to tf32.
// Smem: As[128][36] (row-major m x k), Bs[32][136] (k x n). Conflict-free frags.
// blockIdx.z selects one of up to 3 problem instances (QKV fused).
// ---------------------------------------------------------------------------
constexpr int AW = 36;                 // A row pitch (words)
constexpr int BWp = 136;               // B row pitch (words)
constexpr int SAW = 128 * AW;          // 4608 words
constexpr int SBW = 32 * BWp;          // 4352 words
constexpr int STW = SAW + SBW;         // 8960 words per stage
constexpr int NST = 3;
constexpr int GEMM_SMEM = NST * STW * 4;   // 107520 bytes
constexpr int ITERS = 24;              // 768 / 32

template <bool HEADB>
__global__ __launch_bounds__(256, 2) void tgemm_k(
    const float* __restrict__ A0, const float* __restrict__ A1, const float* __restrict__ A2,
    const float* __restrict__ Bm0, const float* __restrict__ Bm1, const float* __restrict__ Bm2,
    const float* __restrict__ bias0, const float* __restrict__ bias1, const float* __restrict__ bias2,
    float* __restrict__ C0, float* __restrict__ C1, float* __restrict__ C2,
    int M, int N, int K)
{
    extern __shared__ float smf[];
    const uint32_t smb = (uint32_t)__cvta_generic_to_shared(smf);

    const int z = blockIdx.z;
    const float* A    = (z == 0) ? A0    : (z == 1) ? A1    : A2;
    const float* Bm   = (z == 0) ? Bm0   : (z == 1) ? Bm1   : Bm2;
    const float* bias = (z == 0) ? bias0 : (z == 1) ? bias1 : bias2;
    float*       C    = (z == 0) ? C0    : (z == 1) ? C1    : C2;

    const int t    = threadIdx.x;
    const int m0   = blockIdx.y * 128;
    const int n0   = blockIdx.x * 128;
    const int warp = t >> 5;
    const int lane = t & 31;
    const int wm   = (warp >> 2) * 64;   // 2 warps in m
    const int wn   = (warp & 3) * 32;    // 4 warps in n
    const int group = lane >> 2;
    const int tig   = lane & 3;

    // loader addressing (16B chunks)
    const int ar = t >> 3;           // A rows ar + i*32
    const int ac = (t & 7) * 4;      // A k-col (words)
    const int br = t >> 3;           // B k-row (0..31)
    const int bc = (t & 7) * 4;      // B n-col chunks bc + j*32

    auto issue_stage = [&](int s, int k0) {
        const uint32_t abase = smb + (uint32_t)(s * STW) * 4;
        const uint32_t bbase = abase + SAW * 4;
#pragma unroll
        for (int i = 0; i < 4; i++) {
            int r = ar + i * 32;
            cpa16(abase + (uint32_t)(r * AW + ac) * 4,
                  &A[(size_t)(m0 + r) * K + k0 + ac]);
        }
#pragma unroll
        for (int j = 0; j < 4; j++) {
            int col = bc + j * 32;
            const float* src;
            if (HEADB)
                src = Bm + (size_t)((n0 + col) >> 6) * K * 64
                         + (size_t)(k0 + br) * 64 + (col & 63);
            else
                src = Bm + (size_t)(k0 + br) * N + n0 + col;
            cpa16(bbase + (uint32_t)(br * BWp + col) * 4, src);
        }
        CP_COMMIT();
    };

    float acc[4][4][4];
#pragma unroll
    for (int mt = 0; mt < 4; mt++)
#pragma unroll
        for (int nt = 0; nt < 4; nt++)
#pragma unroll
            for (int j = 0; j < 4; j++) acc[mt][nt][j] = 0.0f;

    issue_stage(0, 0);
    issue_stage(1, 32);

    for (int it = 0; it < ITERS; it++) {
        CP_WAIT1();
        __syncthreads();
        if (it + 2 < ITERS) issue_stage((it + 2) % NST, (it + 2) * 32);
        else                CP_COMMIT();   // empty group keeps wait accounting

        const float* As = smf + (it % NST) * STW;
        const float* Bs = As + SAW;

#pragma unroll
        for (int kk = 0; kk < 4; kk++) {
            const int k8 = kk * 8;
            uint32_t a[4][4], b[4][2];
#pragma unroll
            for (int mt = 0; mt < 4; mt++) {
                int r = wm + mt * 16 + group;
                a[mt][0] = __float_as_uint(As[r * AW + k8 + tig]);
                a[mt][1] = __float_as_uint(As[(r + 8) * AW + k8 + tig]);
                a[mt][2] = __float_as_uint(As[r * AW + k8 + tig + 4]);
                a[mt][3] = __float_as_uint(As[(r + 8) * AW + k8 + tig + 4]);
            }
#pragma unroll
            for (int nt = 0; nt < 4; nt++) {
                int cc = wn + nt * 8 + group;
                b[nt][0] = __float_as_uint(Bs[(k8 + tig) * BWp + cc]);
                b[nt][1] = __float_as_uint(Bs[(k8 + tig + 4) * BWp + cc]);
            }
#pragma unroll
            for (int mt = 0; mt < 4; mt++)
#pragma unroll
                for (int nt = 0; nt < 4; nt++) {
                    asm volatile(
                        "mma.sync.aligned.m16n8k8.row.col.f32.tf32.tf32.f32 "
                        "{%0,%1,%2,%3}, {%4,%5,%6,%7}, {%8,%9}, {%0,%1,%2,%3};\n"
                        : "+f"(acc[mt][nt][0]), "+f"(acc[mt][nt][1]),
                          "+f"(acc[mt][nt][2]), "+f"(acc[mt][nt][3])
                        : "r"(a[mt][0]), "r"(a[mt][1]), "r"(a[mt][2]), "r"(a[mt][3]),
                          "r"(b[nt][0]), "r"(b[nt][1]));
                }
        }
    }

#pragma unroll
    for (int mt = 0; mt < 4; mt++) {
#pragma unroll
        for (int nt = 0; nt < 4; nt++) {
            int col  = n0 + wn + nt * 8 + tig * 2;
            float bx = bias[col];
            float by = bias[col + 1];
            int r0 = m0 + wm + mt * 16 + group;
            float2 o0 = make_float2(acc[mt][nt][0] + bx, acc[mt][nt][1] + by);
            float2 o1 = make_float2(acc[mt][nt][2] + bx, acc[mt][nt][3] + by);
            *(float2*)&C[(size_t)r0 * N + col]       = o0;
            *(float2*)&C[(size_t)(r0 + 8) * N + col] = o1;
        }
    }
}

// ---------------------------------------------------------------------------
// Rotary (full head, ROT == DH == 64). Pair (i, i+32) shares angle pos/freq[i].
// ---------------------------------------------------------------------------
__global__ __launch_bounds__(256) void rotary_k(float* __restrict__ Q,
                                                float* __restrict__ K)
{
    const int total_half = Bb * Ss * Hh * 32;
    int tid = blockIdx.x * blockDim.x + threadIdx.x;
    if (tid >= 2 * total_half) return;

    float* buf = (tid < total_half) ? Q : K;
    int id  = (tid < total_half) ? tid : tid - total_half;
    int i   = id & 31;
    int bsh = id >> 5;
    int s   = (bsh / Hh) % Ss;

    float inv_freq = expf(-(float)(2 * i) * (1.0f / 64.0f) * 9.210340371976184f);
    float ang = (float)s * inv_freq;
    float sn, cs;
    sincosf(ang, &sn, &cs);

    size_t base = (size_t)bsh * 64;
    float x = buf[base + i];
    float y = buf[base + i + 32];
    buf[base + i]      = x * cs - y * sn;
    buf[base + i + 32] = y * cs + x * sn;
}

// ---------------------------------------------------------------------------
// Sliding-window attention with packed f32x2 FFMA. Z output pre-rounded tf32.
// ---------------------------------------------------------------------------
constexpr int QP  = 65;
constexpr int KP  = 65;
constexpr int VP  = 68;
constexpr int SCP = 196;

__global__ __launch_bounds__(256) void attn_k(
    const float* __restrict__ Q, const float* __restrict__ K,
    const float* __restrict__ V, float* __restrict__ Z)
{
    extern __shared__ float sm[];
    float* Qs  = sm;
    float* KVs = sm + 64 * QP;
    float* Sc  = sm + 64 * QP + 64 * VP;

    const int t  = threadIdx.x;
    const int q0 = blockIdx.x * 64;
    const int h  = blockIdx.y;
    const int b  = blockIdx.z;

    const int ty4 = (t >> 4) * 4;
    const int tx4 = (t & 15) * 4;

#pragma unroll
    for (int i = 0; i < 4; i++) {
        int idx = t + i * 256;
        int r = idx >> 4;
        int c = (idx & 15) * 4;
        float4 v = *(const float4*)&Q[(((size_t)(b * Ss + q0 + r)) * Hh + h) * 64 + c];
        Qs[r * QP + c + 0] = v.x;
        Qs[r * QP + c + 1] = v.y;
        Qs[r * QP + c + 2] = v.z;
        Qs[r * QP + c + 3] = v.w;
    }

    for (int c = 0; c < 3; c++) {
        const int j0 = q0 - 128 + c * 64;
        __syncthreads();
#pragma unroll
        for (int i = 0; i < 4; i++) {
            int idx = t + i * 256;
            int r = idx >> 4;
            int cc = (idx & 15) * 4;
            int jg = j0 + r;
            float4 v = make_float4(0.f, 0.f, 0.f, 0.f);
            if (jg >= 0)
                v = *(const float4*)&K[(((size_t)(b * Ss + jg)) * Hh + h) * 64 + cc];
            KVs[r * KP + cc + 0] = v.x;
            KVs[r * KP + cc + 1] = v.y;
            KVs[r * KP + cc + 2] = v.z;
            KVs[r * KP + cc + 3] = v.w;
        }
        __syncthreads();

        ull accp[4][2];
#pragma unroll
        for (int i = 0; i < 4; i++) { accp[i][0] = 0ull; accp[i][1] = 0ull; }

#pragma unroll 4
        for (int d = 0; d < 64; d++) {
            float k0v = KVs[(tx4 + 0) * KP + d];
            float k1v = KVs[(tx4 + 1) * KP + d];
            float k2v = KVs[(tx4 + 2) * KP + d];
            float k3v = KVs[(tx4 + 3) * KP + d];
            ull kb0 = pack2(k0v, k1v);
            ull kb1 = pack2(k2v, k3v);
#pragma unroll
            for (int i = 0; i < 4; i++) {
                float av = Qs[(ty4 + i) * QP + d];
                ull ab = pack2(av, av);
                ffma2(accp[i][0], ab, kb0);
                ffma2(accp[i][1], ab, kb1);
            }
        }

#pragma unroll
        for (int i = 0; i < 4; i++) {
            float s0, s1, s2, s3;
            unpack2(accp[i][0], s0, s1);
            unpack2(accp[i][1], s2, s3);
            float sv[4] = {s0, s1, s2, s3};
            int qg = q0 + ty4 + i;
#pragma unroll
            for (int j = 0; j < 4; j++) {
                int jg = j0 + tx4 + j;
                bool ok = (jg >= 0) && (jg <= qg) && (jg > qg - WIN);
                Sc[(ty4 + i) * SCP + c * 64 + tx4 + j] = ok ? sv[j] * 0.125f : -1e30f;
            }
        }
    }
    __syncthreads();

    {
        int r = t >> 2;
        int p = t & 3;
        float mx = -1e30f;
        for (int jj = p * 48; jj < p * 48 + 48; jj++)
            mx = fmaxf(mx, Sc[r * SCP + jj]);
        mx = fmaxf(mx, __shfl_xor_sync(0xFFFFFFFFu, mx, 1));
        mx = fmaxf(mx, __shfl_xor_sync(0xFFFFFFFFu, mx, 2));
        float sum = 0.0f;
        for (int jj = p * 48; jj < p * 48 + 48; jj++) {
            float e = __expf(Sc[r * SCP + jj] - mx);
            Sc[r * SCP + jj] = e;
            sum += e;
        }
        sum += __shfl_xor_sync(0xFFFFFFFFu, sum, 1);
        sum += __shfl_xor_sync(0xFFFFFFFFu, sum, 2);
        float inv = 1.0f / sum;
        for (int jj = p * 48; jj < p * 48 + 48; jj++)
            Sc[r * SCP + jj] *= inv;
    }

    ull op[4][2];
#pragma unroll
    for (int i = 0; i < 4; i++) { op[i][0] = 0ull; op[i][1] = 0ull; }

    for (int c = 0; c < 3; c++) {
        const int j0 = q0 - 128 + c * 64;
        __syncthreads();
#pragma unroll
        for (int i = 0; i < 4; i++) {
            int idx = t + i * 256;
            int r = idx >> 4;
            int cc = (idx & 15) * 4;
            int jg = j0 + r;
            float4 v = make_float4(0.f, 0.f, 0.f, 0.f);
            if (jg >= 0)
                v = *(const float4*)&V[(((size_t)(b * Ss + jg)) * Hh + h) * 64 + cc];
            *(float4*)&KVs[r * VP + cc] = v;
        }
        __syncthreads();

#pragma unroll 4
        for (int jj = 0; jj < 64; jj++) {
            ulonglong2 vb = *(const ulonglong2*)&KVs[jj * VP + tx4];
#pragma unroll
            for (int i = 0; i < 4; i++) {
                float pv = Sc[(ty4 + i) * SCP + c * 64 + jj];
                ull pb = pack2(pv, pv);
                ffma2(op[i][0], pb, vb.x);
                ffma2(op[i][1], pb, vb.y);
            }
        }
    }

#pragma unroll
    for (int i = 0; i < 4; i++) {
        float4 o;
        unpack2(op[i][0], o.x, o.y);
        unpack2(op[i][1], o.z, o.w);
        o.x = round_tf32(o.x); o.y = round_tf32(o.y);
        o.z = round_tf32(o.z); o.w = round_tf32(o.w);
        *(float4*)&Z[(((size_t)(b * Ss + q0 + ty4 + i)) * Hh + h) * 64 + tx4] = o;
    }
}

// ---------------------------------------------------------------------------
extern "C" void kernel_launch(void* const* d_in, const int* in_sizes, int n_in,
                              void* d_out, int out_size)
{
    const float* qin = (const float*)d_in[0];
    const float* kin = (const float*)d_in[1];
    const float* vin = (const float*)d_in[2];
    const float* WQ  = (const float*)d_in[3];
    const float* WK  = (const float*)d_in[4];
    const float* WV  = (const float*)d_in[5];
    const float* WO  = (const float*)d_in[6];
    const float* bQ  = (const float*)d_in[7];
    const float* bK  = (const float*)d_in[8];
    const float* bV  = (const float*)d_in[9];
    const float* bO  = (const float*)d_in[10];
    float* out = (float*)d_out;

    float *pQ, *pK, *pV, *pZ;
    float *pAq, *pAk, *pAv, *pWq, *pWk, *pWv, *pWo;
    cudaGetSymbolAddress((void**)&pQ, g_Q);
    cudaGetSymbolAddress((void**)&pK, g_K);
    cudaGetSymbolAddress((void**)&pV, g_V);
    cudaGetSymbolAddress((void**)&pZ, g_Z);
    cudaGetSymbolAddress((void**)&pAq, g_Aq);
    cudaGetSymbolAddress((void**)&pAk, g_Ak);
    cudaGetSymbolAddress((void**)&pAv, g_Av);
    cudaGetSymbolAddress((void**)&pWq, g_Wq);
    cudaGetSymbolAddress((void**)&pWk, g_Wk);
    cudaGetSymbolAddress((void**)&pWv, g_Wv);
    cudaGetSymbolAddress((void**)&pWo, g_Wo);

    const int M = Bb * Ss;       // 4096
    const int N = Hh * DHd;      // 768
    const int Kd = Dd;           // 768

    size_t asmem = (size_t)(64 * QP + 64 * VP + 64 * SCP) * sizeof(float);
    cudaFuncSetAttribute(tgemm_k<true>,
                         cudaFuncAttributeMaxDynamicSharedMemorySize, GEMM_SMEM);
    cudaFuncSetAttribute(tgemm_k<false>,
                         cudaFuncAttributeMaxDynamicSharedMemorySize, GEMM_SMEM);
    cudaFuncSetAttribute(attn_k,
                         cudaFuncAttributeMaxDynamicSharedMemorySize, (int)asmem);

    // Pre-round all GEMM operands to tf32 (RNA)
    round3_k<<<dim3(3072, 3), 256>>>(qin, kin, vin, pAq, pAk, pAv);
    round4_k<<<dim3(576, 4), 256>>>(WQ, WK, WV, WO, pWq, pWk, pWv, pWo);

    // Fused QKV projections (z selects instance); BN=128 grid
    tgemm_k<true><<<dim3(N / 128, M / 128, 3), 256, GEMM_SMEM>>>(
        pAq, pAk, pAv, pWq, pWk, pWv, bQ, bK, bV, pQ, pK, pV, M, N, Kd);

    int rot_threads = 2 * Bb * Ss * Hh * 32;
    rotary_k<<<rot_threads / 256, 256>>>(pQ, pK);

    attn_k<<<dim3(Ss / 64, Hh, Bb), 256, asmem>>>(pQ, pK, pV, pZ);

    // Output projection (Z pre-rounded in attn epilogue)
    tgemm_k<false><<<dim3(N / 128, M / 128, 1), 256, GEMM_SMEM>>>(
        pZ, pZ, pZ, pWo, pWo, pWo, bO, bO, bO, out, out, out, M, N, Kd);
}

// round 8
// speedup vs baseline: 1.2397x; 1.0843x over previous
#include <cuda_runtime.h>
#include <math.h>
#include <stdint.h>

// Problem constants
constexpr int Bb = 2;
constexpr int Ss = 2048;
constexpr int Dd = 768;
constexpr int Hh = 12;
constexpr int DHd = 64;
constexpr int WIN = 128;

// Scratch (device globals; no allocation allowed)
__device__ __align__(16) float g_Q[Bb * Ss * Hh * DHd];
__device__ __align__(16) float g_K[Bb * Ss * Hh * DHd];
__device__ __align__(16) float g_V[Bb * Ss * Hh * DHd];
__device__ __align__(16) float g_Z[Bb * Ss * Hh * DHd];
// tf32-pre-rounded operands
__device__ __align__(16) float g_Aq[Bb * Ss * Dd];
__device__ __align__(16) float g_Ak[Bb * Ss * Dd];
__device__ __align__(16) float g_Av[Bb * Ss * Dd];
__device__ __align__(16) float g_Wq[Hh * Dd * DHd];
__device__ __align__(16) float g_Wk[Hh * Dd * DHd];
__device__ __align__(16) float g_Wv[Hh * Dd * DHd];
__device__ __align__(16) float g_Wo[Hh * DHd * Dd];
// rotary sin/cos table: [pos][freq] -> (sin, cos)
__device__ __align__(16) float2 g_T[Ss * 32];

using ull = unsigned long long;

__device__ __forceinline__ uint32_t f2tf32(float x) {
    uint32_t u;
    asm("cvt.rna.tf32.f32 %0, %1;" : "=r"(u) : "f"(x));
    return u;
}
__device__ __forceinline__ float round_tf32(float x) {
    return __uint_as_float(f2tf32(x));
}
__device__ __forceinline__ ull pack2(float x, float y) {
    ull r;
    asm("mov.b64 %0, {%1, %2};" : "=l"(r) : "f"(x), "f"(y));
    return r;
}
__device__ __forceinline__ void unpack2(ull v, float& x, float& y) {
    asm("mov.b64 {%0, %1}, %2;" : "=f"(x), "=f"(y) : "l"(v));
}
__device__ __forceinline__ void ffma2(ull& d, ull a, ull b) {
    asm("fma.rn.f32x2 %0, %1, %2, %0;" : "+l"(d) : "l"(a), "l"(b));
}
__device__ __forceinline__ void cpa16(uint32_t dst, const void* src) {
    asm volatile("cp.async.cg.shared.global [%0], [%1], 16;"
                 :: "r"(dst), "l"(src) : "memory");
}
#define CP_COMMIT() asm volatile("cp.async.commit_group;" ::: "memory")
#define CP_WAIT1()  asm volatile("cp.async.wait_group 1;" ::: "memory")

// ---------------------------------------------------------------------------
// Pre-rounding kernels + rotary table init.
// ---------------------------------------------------------------------------
__global__ __launch_bounds__(256) void round3_k(
    const float* __restrict__ a, const float* __restrict__ b,
    const float* __restrict__ c,
    float* __restrict__ da, float* __restrict__ db, float* __restrict__ dc)
{
    int idx = blockIdx.x * 256 + threadIdx.x;
    const float* s = (blockIdx.y == 0) ? a : (blockIdx.y == 1) ? b : c;
    float*       d = (blockIdx.y == 0) ? da : (blockIdx.y == 1) ? db : dc;
    float4 v = ((const float4*)s)[idx];
    v.x = round_tf32(v.x); v.y = round_tf32(v.y);
    v.z = round_tf32(v.z); v.w = round_tf32(v.w);
    ((float4*)d)[idx] = v;
}
__global__ __launch_bounds__(256) void round4_k(
    const float* __restrict__ a, const float* __restrict__ b,
    const float* __restrict__ c, const float* __restrict__ e,
    float* __restrict__ da, float* __restrict__ db,
    float* __restrict__ dc, float* __restrict__ de)
{
    int idx = blockIdx.x * 256 + threadIdx.x;
    const float* s = (blockIdx.y == 0) ? a : (blockIdx.y == 1) ? b
                   : (blockIdx.y == 2) ? c : e;
    float*       d = (blockIdx.y == 0) ? da : (blockIdx.y == 1) ? db
                   : (blockIdx.y == 2) ? dc : de;
    float4 v = ((const float4*)s)[idx];
    v.x = round_tf32(v.x); v.y = round_tf32(v.y);
    v.z = round_tf32(v.z); v.w = round_tf32(v.w);
    ((float4*)d)[idx] = v;
}
__global__ __launch_bounds__(256) void table_k(float2* __restrict__ T)
{
    int tid = blockIdx.x * 256 + threadIdx.x;   // 0 .. 2048*32-1
    int s = tid >> 5;
    int i = tid & 31;
    float inv_freq = expf(-(float)(2 * i) * (1.0f / 64.0f) * 9.210340371976184f);
    float ang = (float)s * inv_freq;
    float sn, cs;
    sincosf(ang, &sn, &cs);
    T[tid] = make_float2(sn, cs);
}

// ---------------------------------------------------------------------------
// tf32 mma GEMM, cp.async 3-stage, BM=128 BN=128 BK=32, 256 thr = 8 warps.
// (unchanged from round 7)
// ---------------------------------------------------------------------------
constexpr int AW = 36;
constexpr int BWp = 136;
constexpr int SAW = 128 * AW;
constexpr int SBW = 32 * BWp;
constexpr int STW = SAW + SBW;
constexpr int NST = 3;
constexpr int GEMM_SMEM = NST * STW * 4;
constexpr int ITERS = 24;

template <bool HEADB>
__global__ __launch_bounds__(256, 2) void tgemm_k(
    const float* __restrict__ A0, const float* __restrict__ A1, const float* __restrict__ A2,
    const float* __restrict__ Bm0, const float* __restrict__ Bm1, const float* __restrict__ Bm2,
    const float* __restrict__ bias0, const float* __restrict__ bias1, const float* __restrict__ bias2,
    float* __restrict__ C0, float* __restrict__ C1, float* __restrict__ C2,
    int M, int N, int K)
{
    extern __shared__ float smf[];
    const uint32_t smb = (uint32_t)__cvta_generic_to_shared(smf);

    const int z = blockIdx.z;
    const float* A    = (z == 0) ? A0    : (z == 1) ? A1    : A2;
    const float* Bm   = (z == 0) ? Bm0   : (z == 1) ? Bm1   : Bm2;
    const float* bias = (z == 0) ? bias0 : (z == 1) ? bias1 : bias2;
    float*       C    = (z == 0) ? C0    : (z == 1) ? C1    : C2;

    const int t    = threadIdx.x;
    const int m0   = blockIdx.y * 128;
    const int n0   = blockIdx.x * 128;
    const int warp = t >> 5;
    const int lane = t & 31;
    const int wm   = (warp >> 2) * 64;
    const int wn   = (warp & 3) * 32;
    const int group = lane >> 2;
    const int tig   = lane & 3;

    const int ar = t >> 3;
    const int ac = (t & 7) * 4;
    const int br = t >> 3;
    const int bc = (t & 7) * 4;

    auto issue_stage = [&](int s, int k0) {
        const uint32_t abase = smb + (uint32_t)(s * STW) * 4;
        const uint32_t bbase = abase + SAW * 4;
#pragma unroll
        for (int i = 0; i < 4; i++) {
            int r = ar + i * 32;
            cpa16(abase + (uint32_t)(r * AW + ac) * 4,
                  &A[(size_t)(m0 + r) * K + k0 + ac]);
        }
#pragma unroll
        for (int j = 0; j < 4; j++) {
            int col = bc + j * 32;
            const float* src;
            if (HEADB)
                src = Bm + (size_t)((n0 + col) >> 6) * K * 64
                         + (size_t)(k0 + br) * 64 + (col & 63);
            else
                src = Bm + (size_t)(k0 + br) * N + n0 + col;
            cpa16(bbase + (uint32_t)(br * BWp + col) * 4, src);
        }
        CP_COMMIT();
    };

    float acc[4][4][4];
#pragma unroll
    for (int mt = 0; mt < 4; mt++)
#pragma unroll
        for (int nt = 0; nt < 4; nt++)
#pragma unroll
            for (int j = 0; j < 4; j++) acc[mt][nt][j] = 0.0f;

    issue_stage(0, 0);
    issue_stage(1, 32);

    for (int it = 0; it < ITERS; it++) {
        CP_WAIT1();
        __syncthreads();
        if (it + 2 < ITERS) issue_stage((it + 2) % NST, (it + 2) * 32);
        else                CP_COMMIT();

        const float* As = smf + (it % NST) * STW;
        const float* Bs = As + SAW;

#pragma unroll
        for (int kk = 0; kk < 4; kk++) {
            const int k8 = kk * 8;
            uint32_t a[4][4], b[4][2];
#pragma unroll
            for (int mt = 0; mt < 4; mt++) {
                int r = wm + mt * 16 + group;
                a[mt][0] = __float_as_uint(As[r * AW + k8 + tig]);
                a[mt][1] = __float_as_uint(As[(r + 8) * AW + k8 + tig]);
                a[mt][2] = __float_as_uint(As[r * AW + k8 + tig + 4]);
                a[mt][3] = __float_as_uint(As[(r + 8) * AW + k8 + tig + 4]);
            }
#pragma unroll
            for (int nt = 0; nt < 4; nt++) {
                int cc = wn + nt * 8 + group;
                b[nt][0] = __float_as_uint(Bs[(k8 + tig) * BWp + cc]);
                b[nt][1] = __float_as_uint(Bs[(k8 + tig + 4) * BWp + cc]);
            }
#pragma unroll
            for (int mt = 0; mt < 4; mt++)
#pragma unroll
                for (int nt = 0; nt < 4; nt++) {
                    asm volatile(
                        "mma.sync.aligned.m16n8k8.row.col.f32.tf32.tf32.f32 "
                        "{%0,%1,%2,%3}, {%4,%5,%6,%7}, {%8,%9}, {%0,%1,%2,%3};\n"
                        : "+f"(acc[mt][nt][0]), "+f"(acc[mt][nt][1]),
                          "+f"(acc[mt][nt][2]), "+f"(acc[mt][nt][3])
                        : "r"(a[mt][0]), "r"(a[mt][1]), "r"(a[mt][2]), "r"(a[mt][3]),
                          "r"(b[nt][0]), "r"(b[nt][1]));
                }
        }
    }

#pragma unroll
    for (int mt = 0; mt < 4; mt++) {
#pragma unroll
        for (int nt = 0; nt < 4; nt++) {
            int col  = n0 + wn + nt * 8 + tig * 2;
            float bx = bias[col];
            float by = bias[col + 1];
            int r0 = m0 + wm + mt * 16 + group;
            float2 o0 = make_float2(acc[mt][nt][0] + bx, acc[mt][nt][1] + by);
            float2 o1 = make_float2(acc[mt][nt][2] + bx, acc[mt][nt][3] + by);
            *(float2*)&C[(size_t)r0 * N + col]       = o0;
            *(float2*)&C[(size_t)(r0 + 8) * N + col] = o1;
        }
    }
}

// ---------------------------------------------------------------------------
// Sliding-window attention, d-major score phase, fused rotary (table-based).
// Smem (floats): Qd[64][68] @0 | KV @4352 (64*136, reused: K2d then V[64][68])
//                | Sc[64][196] @13056.  Total 25600 floats = 102400 B.
// ---------------------------------------------------------------------------
constexpr int QDW = 68;    // Qd row width (d-major: [d][q])
constexpr int KVW = 136;   // K2d row width (d-major: [d][key], 128 keys)
constexpr int VP  = 68;    // V row width (key-major: [key][d])
constexpr int SCP = 196;
constexpr int OFF_KV = 64 * QDW;            // 4352
constexpr int OFF_SC = OFF_KV + 64 * KVW;   // 13056
constexpr int ATTN_SMEM = (OFF_SC + 64 * SCP) * 4;   // 102400 B

__global__ __launch_bounds__(256) void attn_k(
    const float* __restrict__ Q, const float* __restrict__ K,
    const float* __restrict__ V, const float2* __restrict__ T,
    float* __restrict__ Z)
{
    extern __shared__ float sm[];
    float* Qd = sm;
    float* KV = sm + OFF_KV;
    float* Sc = sm + OFF_SC;

    const int t  = threadIdx.x;
    const int q0 = blockIdx.x * 64;
    const int h  = blockIdx.y;
    const int b  = blockIdx.z;

    const int ty   = t >> 5;        // 0..7  (score-phase q-group; warp-uniform)
    const int lane = t & 31;

    // ---- load Q (rotated, d-major transposed) ----
    {
#pragma unroll
        for (int w = 0; w < 2; w++) {
            int idx = t + w * 256;          // 0..511
            int row = idx >> 3;             // q row 0..63
            int c4  = (idx & 7) * 4;        // d in [0,32)
            int qg  = q0 + row;
            const float* src = &Q[(((size_t)(b * Ss + qg)) * Hh + h) * 64];
            float4 x = *(const float4*)&src[c4];
            float4 y = *(const float4*)&src[c4 + 32];
            float xa[4] = {x.x, x.y, x.z, x.w};
            float ya[4] = {y.x, y.y, y.z, y.w};
#pragma unroll
            for (int j = 0; j < 4; j++) {
                float2 sc = T[qg * 32 + c4 + j];
                Qd[(c4 + j) * QDW + row]      = xa[j] * sc.y - ya[j] * sc.x;
                Qd[(c4 + j + 32) * QDW + row] = ya[j] * sc.y + xa[j] * sc.x;
            }
        }
    }
    // ---- load K pair-window (128 keys: q0-128 .. q0-1), rotated, d-major ----
    {
#pragma unroll
        for (int w = 0; w < 4; w++) {
            int idx = t + w * 256;          // 0..1023
            int key = idx >> 3;             // 0..127
            int c4  = (idx & 7) * 4;
            int jg  = q0 - 128 + key;
            if (jg >= 0) {
                const float* src = &K[(((size_t)(b * Ss + jg)) * Hh + h) * 64];
                float4 x = *(const float4*)&src[c4];
                float4 y = *(const float4*)&src[c4 + 32];
                float xa[4] = {x.x, x.y, x.z, x.w};
                float ya[4] = {y.x, y.y, y.z, y.w};
#pragma unroll
                for (int j = 0; j < 4; j++) {
                    float2 sc = T[jg * 32 + c4 + j];
                    KV[(c4 + j) * KVW + key]      = xa[j] * sc.y - ya[j] * sc.x;
                    KV[(c4 + j + 32) * KVW + key] = ya[j] * sc.y + xa[j] * sc.x;
                }
            } else {
#pragma unroll
                for (int j = 0; j < 4; j++) {
                    KV[(c4 + j) * KVW + key]      = 0.0f;
                    KV[(c4 + j + 32) * KVW + key] = 0.0f;
                }
            }
        }
    }
    __syncthreads();

    // ---- score pair pass: 8q x 4k per thread over 128-key window ----
    {
        ull accp[8][2];
#pragma unroll
        for (int i = 0; i < 8; i++) { accp[i][0] = 0ull; accp[i][1] = 0ull; }
        const int qb = ty * 8;
#pragma unroll 8
        for (int d = 0; d < 64; d++) {
            float4 kv = *(const float4*)&KV[d * KVW + lane * 4];
            ull kb0 = pack2(kv.x, kv.y);
            ull kb1 = pack2(kv.z, kv.w);
            float4 qa = *(const float4*)&Qd[d * QDW + qb];
            float4 qc = *(const float4*)&Qd[d * QDW + qb + 4];
            float qv[8] = {qa.x, qa.y, qa.z, qa.w, qc.x, qc.y, qc.z, qc.w};
#pragma unroll
            for (int i = 0; i < 8; i++) {
                ull ab = pack2(qv[i], qv[i]);
                ffma2(accp[i][0], ab, kb0);
                ffma2(accp[i][1], ab, kb1);
            }
        }
#pragma unroll
        for (int i = 0; i < 8; i++) {
            float s0, s1, s2, s3;
            unpack2(accp[i][0], s0, s1);
            unpack2(accp[i][1], s2, s3);
            float sv[4] = {s0, s1, s2, s3};
            int qg = q0 + qb + i;
            float4 o;
            float* op = &o.x;
#pragma unroll
            for (int j = 0; j < 4; j++) {
                int jg = q0 - 128 + lane * 4 + j;
                bool ok = (jg >= 0) && (jg > qg - WIN);   // jg <= qg always here
                op[j] = ok ? sv[j] * 0.125f : -1e30f;
            }
            *(float4*)&Sc[(qb + i) * SCP + lane * 4] = o;
        }
    }
    __syncthreads();

    // ---- load K diagonal chunk (keys q0 .. q0+63) over KV cols 0..63 ----
    {
#pragma unroll
        for (int w = 0; w < 2; w++) {
            int idx = t + w * 256;
            int key = idx >> 3;             // 0..63
            int c4  = (idx & 7) * 4;
            int jg  = q0 + key;
            const float* src = &K[(((size_t)(b * Ss + jg)) * Hh + h) * 64];
            float4 x = *(const float4*)&src[c4];
            float4 y = *(const float4*)&src[c4 + 32];
            float xa[4] = {x.x, x.y, x.z, x.w};
            float ya[4] = {y.x, y.y, y.z, y.w};
#pragma unroll
            for (int j = 0; j < 4; j++) {
                float2 sc = T[jg * 32 + c4 + j];
                KV[(c4 + j) * KVW + key]      = xa[j] * sc.y - ya[j] * sc.x;
                KV[(c4 + j + 32) * KVW + key] = ya[j] * sc.y + xa[j] * sc.x;
            }
        }
    }
    __syncthreads();

    // ---- score diagonal pass: 8q x 2k per thread over 64 keys ----
    {
        ull acc2[8];
#pragma unroll
        for (int i = 0; i < 8; i++) acc2[i] = 0ull;
        const int qb = ty * 8;
#pragma unroll 8
        for (int d = 0; d < 64; d++) {
            float2 kv = *(const float2*)&KV[d * KVW + lane * 2];
            ull kb = pack2(kv.x, kv.y);
            float4 qa = *(const float4*)&Qd[d * QDW + qb];
            float4 qc = *(const float4*)&Qd[d * QDW + qb + 4];
            float qv[8] = {qa.x, qa.y, qa.z, qa.w, qc.x, qc.y, qc.z, qc.w};
#pragma unroll
            for (int i = 0; i < 8; i++) {
                ull ab = pack2(qv[i], qv[i]);
                ffma2(acc2[i], ab, kb);
            }
        }
#pragma unroll
        for (int i = 0; i < 8; i++) {
            float s0, s1;
            unpack2(acc2[i], s0, s1);
            float sv[2] = {s0, s1};
            int qg = q0 + qb + i;
            float2 o;
            float* op = &o.x;
#pragma unroll
            for (int j = 0; j < 2; j++) {
                int jg = q0 + lane * 2 + j;
                bool ok = (jg <= qg);                    // jg > qg-WIN always here
                op[j] = ok ? sv[j] * 0.125f : -1e30f;
            }
            *(float2*)&Sc[(qb + i) * SCP + 128 + lane * 2] = o;
        }
    }
    __syncthreads();

    // ---- softmax: 4 threads per row, 48 cols each ----
    {
        int r = t >> 2;
        int p = t & 3;
        float mx = -1e30f;
        for (int jj = p * 48; jj < p * 48 + 48; jj++)
            mx = fmaxf(mx, Sc[r * SCP + jj]);
        mx = fmaxf(mx, __shfl_xor_sync(0xFFFFFFFFu, mx, 1));
        mx = fmaxf(mx, __shfl_xor_sync(0xFFFFFFFFu, mx, 2));
        float sum = 0.0f;
        for (int jj = p * 48; jj < p * 48 + 48; jj++) {
            float e = __expf(Sc[r * SCP + jj] - mx);
            Sc[r * SCP + jj] = e;
            sum += e;
        }
        sum += __shfl_xor_sync(0xFFFFFFFFu, sum, 1);
        sum += __shfl_xor_sync(0xFFFFFFFFu, sum, 2);
        float inv = 1.0f / sum;
        for (int jj = p * 48; jj < p * 48 + 48; jj++)
            Sc[r * SCP + jj] *= inv;
    }

    // ---- P @ V (3 chunks of 64 keys; V row-major in KV region) ----
    const int ty4 = (t >> 4) * 4;
    const int tx4 = (t & 15) * 4;
    ull op[4][2];
#pragma unroll
    for (int i = 0; i < 4; i++) { op[i][0] = 0ull; op[i][1] = 0ull; }

    for (int c = 0; c < 3; c++) {
        const int j0 = q0 - 128 + c * 64;
        __syncthreads();
#pragma unroll
        for (int i = 0; i < 4; i++) {
            int idx = t + i * 256;
            int r = idx >> 4;
            int cc = (idx & 15) * 4;
            int jg = j0 + r;
            float4 v = make_float4(0.f, 0.f, 0.f, 0.f);
            if (jg >= 0)
                v = *(const float4*)&V[(((size_t)(b * Ss + jg)) * Hh + h) * 64 + cc];
            *(float4*)&KV[r * VP + cc] = v;
        }
        __syncthreads();

#pragma unroll 4
        for (int jj = 0; jj < 64; jj++) {
            ulonglong2 vb = *(const ulonglong2*)&KV[jj * VP + tx4];
#pragma unroll
            for (int i = 0; i < 4; i++) {
                float pv = Sc[(ty4 + i) * SCP + c * 64 + jj];
                ull pb = pack2(pv, pv);
                ffma2(op[i][0], pb, vb.x);
                ffma2(op[i][1], pb, vb.y);
            }
        }
    }

#pragma unroll
    for (int i = 0; i < 4; i++) {
        float4 o;
        unpack2(op[i][0], o.x, o.y);
        unpack2(op[i][1], o.z, o.w);
        o.x = round_tf32(o.x); o.y = round_tf32(o.y);
        o.z = round_tf32(o.z); o.w = round_tf32(o.w);
        *(float4*)&Z[(((size_t)(b * Ss + q0 + ty4 + i)) * Hh + h) * 64 + tx4] = o;
    }
}

// ---------------------------------------------------------------------------
extern "C" void kernel_launch(void* const* d_in, const int* in_sizes, int n_in,
                              void* d_out, int out_size)
{
    const float* qin = (const float*)d_in[0];
    const float* kin = (const float*)d_in[1];
    const float* vin = (const float*)d_in[2];
    const float* WQ  = (const float*)d_in[3];
    const float* WK  = (const float*)d_in[4];
    const float* WV  = (const float*)d_in[5];
    const float* WO  = (const float*)d_in[6];
    const float* bQ  = (const float*)d_in[7];
    const float* bK  = (const float*)d_in[8];
    const float* bV  = (const float*)d_in[9];
    const float* bO  = (const float*)d_in[10];
    float* out = (float*)d_out;

    float *pQ, *pK, *pV, *pZ;
    float *pAq, *pAk, *pAv, *pWq, *pWk, *pWv, *pWo;
    float2* pT;
    cudaGetSymbolAddress((void**)&pQ, g_Q);
    cudaGetSymbolAddress((void**)&pK, g_K);
    cudaGetSymbolAddress((void**)&pV, g_V);
    cudaGetSymbolAddress((void**)&pZ, g_Z);
    cudaGetSymbolAddress((void**)&pAq, g_Aq);
    cudaGetSymbolAddress((void**)&pAk, g_Ak);
    cudaGetSymbolAddress((void**)&pAv, g_Av);
    cudaGetSymbolAddress((void**)&pWq, g_Wq);
    cudaGetSymbolAddress((void**)&pWk, g_Wk);
    cudaGetSymbolAddress((void**)&pWv, g_Wv);
    cudaGetSymbolAddress((void**)&pWo, g_Wo);
    cudaGetSymbolAddress((void**)&pT, g_T);

    const int M = Bb * Ss;       // 4096
    const int N = Hh * DHd;      // 768
    const int Kd = Dd;           // 768

    cudaFuncSetAttribute(tgemm_k<true>,
                         cudaFuncAttributeMaxDynamicSharedMemorySize, GEMM_SMEM);
    cudaFuncSetAttribute(tgemm_k<false>,
                         cudaFuncAttributeMaxDynamicSharedMemorySize, GEMM_SMEM);
    cudaFuncSetAttribute(attn_k,
                         cudaFuncAttributeMaxDynamicSharedMemorySize, ATTN_SMEM);

    // Pre-round GEMM operands + rotary table
    round3_k<<<dim3(3072, 3), 256>>>(qin, kin, vin, pAq, pAk, pAv);
    round4_k<<<dim3(576, 4), 256>>>(WQ, WK, WV, WO, pWq, pWk, pWv, pWo);
    table_k<<<Ss * 32 / 256, 256>>>(pT);

    // Fused QKV projections
    tgemm_k<true><<<dim3(N / 128, M / 128, 3), 256, GEMM_SMEM>>>(
        pAq, pAk, pAv, pWq, pWk, pWv, bQ, bK, bV, pQ, pK, pV, M, N, Kd);

    // Attention (rotary fused at load)
    attn_k<<<dim3(Ss / 64, Hh, Bb), 256, ATTN_SMEM>>>(pQ, pK, pV, pT, pZ);

    // Output projection
    tgemm_k<false><<<dim3(N / 128, M / 128, 1), 256, GEMM_SMEM>>>(
        pZ, pZ, pZ, pWo, pWo, pWo, bO, bO, bO, out, out, out, M, N, Kd);
}

// round 9
// speedup vs baseline: 1.2799x; 1.0324x over previous
#include <cuda_runtime.h>
#include <math.h>
#include <stdint.h>

// Problem constants
constexpr int Bb = 2;
constexpr int Ss = 2048;
constexpr int Dd = 768;
constexpr int Hh = 12;
constexpr int DHd = 64;
constexpr int WIN = 128;

// Scratch (device globals; no allocation allowed)
__device__ __align__(16) float g_Q[Bb * Ss * Hh * DHd];
__device__ __align__(16) float g_K[Bb * Ss * Hh * DHd];
__device__ __align__(16) float g_V[Bb * Ss * Hh * DHd];
__device__ __align__(16) float g_Z[Bb * Ss * Hh * DHd];
// tf32-pre-rounded operands
__device__ __align__(16) float g_Aq[Bb * Ss * Dd];
__device__ __align__(16) float g_Ak[Bb * Ss * Dd];
__device__ __align__(16) float g_Av[Bb * Ss * Dd];
__device__ __align__(16) float g_Wq[Hh * Dd * DHd];
__device__ __align__(16) float g_Wk[Hh * Dd * DHd];
__device__ __align__(16) float g_Wv[Hh * Dd * DHd];
__device__ __align__(16) float g_Wo[Hh * DHd * Dd];
// rotary sin/cos table: [pos][freq] -> (sin, cos)
__device__ __align__(16) float2 g_T[Ss * 32];

__device__ __forceinline__ uint32_t f2tf32(float x) {
    uint32_t u;
    asm("cvt.rna.tf32.f32 %0, %1;" : "=r"(u) : "f"(x));
    return u;
}
__device__ __forceinline__ float round_tf32(float x) {
    return __uint_as_float(f2tf32(x));
}
__device__ __forceinline__ void cpa16(uint32_t dst, const void* src) {
    asm volatile("cp.async.cg.shared.global [%0], [%1], 16;"
                 :: "r"(dst), "l"(src) : "memory");
}
#define CP_COMMIT() asm volatile("cp.async.commit_group;" ::: "memory")
#define CP_WAIT1()  asm volatile("cp.async.wait_group 1;" ::: "memory")

#define MMA_TF32(acc, a, b)                                                   \
    asm volatile(                                                             \
        "mma.sync.aligned.m16n8k8.row.col.f32.tf32.tf32.f32 "                 \
        "{%0,%1,%2,%3}, {%4,%5,%6,%7}, {%8,%9}, {%0,%1,%2,%3};\n"             \
        : "+f"((acc)[0]), "+f"((acc)[1]), "+f"((acc)[2]), "+f"((acc)[3])      \
        : "r"((a)[0]), "r"((a)[1]), "r"((a)[2]), "r"((a)[3]),                 \
          "r"((b)[0]), "r"((b)[1]))

// ---------------------------------------------------------------------------
// Pre-rounding kernels + rotary table init.
// ---------------------------------------------------------------------------
__global__ __launch_bounds__(256) void round3_k(
    const float* __restrict__ a, const float* __restrict__ b,
    const float* __restrict__ c,
    float* __restrict__ da, float* __restrict__ db, float* __restrict__ dc)
{
    int idx = blockIdx.x * 256 + threadIdx.x;
    const float* s = (blockIdx.y == 0) ? a : (blockIdx.y == 1) ? b : c;
    float*       d = (blockIdx.y == 0) ? da : (blockIdx.y == 1) ? db : dc;
    float4 v = ((const float4*)s)[idx];
    v.x = round_tf32(v.x); v.y = round_tf32(v.y);
    v.z = round_tf32(v.z); v.w = round_tf32(v.w);
    ((float4*)d)[idx] = v;
}
__global__ __launch_bounds__(256) void round4_k(
    const float* __restrict__ a, const float* __restrict__ b,
    const float* __restrict__ c, const float* __restrict__ e,
    float* __restrict__ da, float* __restrict__ db,
    float* __restrict__ dc, float* __restrict__ de)
{
    int idx = blockIdx.x * 256 + threadIdx.x;
    const float* s = (blockIdx.y == 0) ? a : (blockIdx.y == 1) ? b
                   : (blockIdx.y == 2) ? c : e;
    float*       d = (blockIdx.y == 0) ? da : (blockIdx.y == 1) ? db
                   : (blockIdx.y == 2) ? dc : de;
    float4 v = ((const float4*)s)[idx];
    v.x = round_tf32(v.x); v.y = round_tf32(v.y);
    v.z = round_tf32(v.z); v.w = round_tf32(v.w);
    ((float4*)d)[idx] = v;
}
__global__ __launch_bounds__(256) void table_k(float2* __restrict__ T)
{
    int tid = blockIdx.x * 256 + threadIdx.x;
    int s = tid >> 5;
    int i = tid & 31;
    float inv_freq = expf(-(float)(2 * i) * (1.0f / 64.0f) * 9.210340371976184f);
    float ang = (float)s * inv_freq;
    float sn, cs;
    sincosf(ang, &sn, &cs);
    T[tid] = make_float2(sn, cs);
}

// ---------------------------------------------------------------------------
// tf32 mma GEMM, cp.async 3-stage, BM=128 BN=128 BK=32 (unchanged round 8).
// ---------------------------------------------------------------------------
constexpr int AW = 36;
constexpr int BWp = 136;
constexpr int SAW = 128 * AW;
constexpr int SBW = 32 * BWp;
constexpr int STW = SAW + SBW;
constexpr int NST = 3;
constexpr int GEMM_SMEM = NST * STW * 4;
constexpr int ITERS = 24;

template <bool HEADB>
__global__ __launch_bounds__(256, 2) void tgemm_k(
    const float* __restrict__ A0, const float* __restrict__ A1, const float* __restrict__ A2,
    const float* __restrict__ Bm0, const float* __restrict__ Bm1, const float* __restrict__ Bm2,
    const float* __restrict__ bias0, const float* __restrict__ bias1, const float* __restrict__ bias2,
    float* __restrict__ C0, float* __restrict__ C1, float* __restrict__ C2,
    int M, int N, int K)
{
    extern __shared__ float smf[];
    const uint32_t smb = (uint32_t)__cvta_generic_to_shared(smf);

    const int z = blockIdx.z;
    const float* A    = (z == 0) ? A0    : (z == 1) ? A1    : A2;
    const float* Bm   = (z == 0) ? Bm0   : (z == 1) ? Bm1   : Bm2;
    const float* bias = (z == 0) ? bias0 : (z == 1) ? bias1 : bias2;
    float*       C    = (z == 0) ? C0    : (z == 1) ? C1    : C2;

    const int t    = threadIdx.x;
    const int m0   = blockIdx.y * 128;
    const int n0   = blockIdx.x * 128;
    const int warp = t >> 5;
    const int lane = t & 31;
    const int wm   = (warp >> 2) * 64;
    const int wn   = (warp & 3) * 32;
    const int group = lane >> 2;
    const int tig   = lane & 3;

    const int ar = t >> 3;
    const int ac = (t & 7) * 4;
    const int br = t >> 3;
    const int bc = (t & 7) * 4;

    auto issue_stage = [&](int s, int k0) {
        const uint32_t abase = smb + (uint32_t)(s * STW) * 4;
        const uint32_t bbase = abase + SAW * 4;
#pragma unroll
        for (int i = 0; i < 4; i++) {
            int r = ar + i * 32;
            cpa16(abase + (uint32_t)(r * AW + ac) * 4,
                  &A[(size_t)(m0 + r) * K + k0 + ac]);
        }
#pragma unroll
        for (int j = 0; j < 4; j++) {
            int col = bc + j * 32;
            const float* src;
            if (HEADB)
                src = Bm + (size_t)((n0 + col) >> 6) * K * 64
                         + (size_t)(k0 + br) * 64 + (col & 63);
            else
                src = Bm + (size_t)(k0 + br) * N + n0 + col;
            cpa16(bbase + (uint32_t)(br * BWp + col) * 4, src);
        }
        CP_COMMIT();
    };

    float acc[4][4][4];
#pragma unroll
    for (int mt = 0; mt < 4; mt++)
#pragma unroll
        for (int nt = 0; nt < 4; nt++)
#pragma unroll
            for (int j = 0; j < 4; j++) acc[mt][nt][j] = 0.0f;

    issue_stage(0, 0);
    issue_stage(1, 32);

    for (int it = 0; it < ITERS; it++) {
        CP_WAIT1();
        __syncthreads();
        if (it + 2 < ITERS) issue_stage((it + 2) % NST, (it + 2) * 32);
        else                CP_COMMIT();

        const float* As = smf + (it % NST) * STW;
        const float* Bs = As + SAW;

#pragma unroll
        for (int kk = 0; kk < 4; kk++) {
            const int k8 = kk * 8;
            uint32_t a[4][4], b[4][2];
#pragma unroll
            for (int mt = 0; mt < 4; mt++) {
                int r = wm + mt * 16 + group;
                a[mt][0] = __float_as_uint(As[r * AW + k8 + tig]);
                a[mt][1] = __float_as_uint(As[(r + 8) * AW + k8 + tig]);
                a[mt][2] = __float_as_uint(As[r * AW + k8 + tig + 4]);
                a[mt][3] = __float_as_uint(As[(r + 8) * AW + k8 + tig + 4]);
            }
#pragma unroll
            for (int nt = 0; nt < 4; nt++) {
                int cc = wn + nt * 8 + group;
                b[nt][0] = __float_as_uint(Bs[(k8 + tig) * BWp + cc]);
                b[nt][1] = __float_as_uint(Bs[(k8 + tig + 4) * BWp + cc]);
            }
#pragma unroll
            for (int mt = 0; mt < 4; mt++)
#pragma unroll
                for (int nt = 0; nt < 4; nt++)
                    MMA_TF32(acc[mt][nt], a[mt], b[nt]);
        }
    }

#pragma unroll
    for (int mt = 0; mt < 4; mt++) {
#pragma unroll
        for (int nt = 0; nt < 4; nt++) {
            int col  = n0 + wn + nt * 8 + tig * 2;
            float bx = bias[col];
            float by = bias[col + 1];
            int r0 = m0 + wm + mt * 16 + group;
            float2 o0 = make_float2(acc[mt][nt][0] + bx, acc[mt][nt][1] + by);
            float2 o1 = make_float2(acc[mt][nt][2] + bx, acc[mt][nt][3] + by);
            *(float2*)&C[(size_t)r0 * N + col]       = o0;
            *(float2*)&C[(size_t)(r0 + 8) * N + col] = o1;
        }
    }
}

// ---------------------------------------------------------------------------
// Tensor-core sliding-window attention (scores + PV via mma tf32).
// Regions (floats):
//   [0, 4608)      : Qs[64][68] (score A) -> later V[64][72] (PV B)
//   [4608, 17408)  : Kd[64][200] d-major (score B) -> later Sc[64][196]
// ---------------------------------------------------------------------------
constexpr int QSP = 68;    // Qs pitch (4g+tig conflict-free A frags)
constexpr int VPP = 72;    // V pitch  (8tig+group conflict-free B frags)
constexpr int KDP = 200;   // Kd pitch (8tig+group conflict-free B frags)
constexpr int SCP = 196;   // Sc pitch (4g+tig conflict-free A frags)
constexpr int OFF_KS = 64 * VPP;                  // 4608
constexpr int ATTN_SMEM = (OFF_KS + 64 * KDP) * 4;   // 69632 B

__global__ __launch_bounds__(256) void attn_k(
    const float* __restrict__ Q, const float* __restrict__ K,
    const float* __restrict__ V, const float2* __restrict__ T,
    float* __restrict__ Z)
{
    extern __shared__ float sm[];
    float* Qs = sm;             // pitch QSP (score phase)
    float* Vv = sm;             // pitch VPP (PV phase)
    float* Kd = sm + OFF_KS;    // pitch KDP (score phase)
    float* Sc = sm + OFF_KS;    // pitch SCP (after scores)

    const int t  = threadIdx.x;
    const int q0 = blockIdx.x * 64;
    const int h  = blockIdx.y;
    const int b  = blockIdx.z;

    const int warp  = t >> 5;
    const int lane  = t & 31;
    const int group = lane >> 2;
    const int tig   = lane & 3;

    // ---- Q loader: rotated + tf32-rounded, q-major [q][d] ----
#pragma unroll
    for (int pass = 0; pass < 2; pass++) {
        int id  = pass * 8 + warp;       // 0..15
        int c4  = (id >> 1) * 4;         // 0..28
        int row = (id & 1) * 32 + lane;  // 0..63
        int qg  = q0 + row;
        const float* src = &Q[(((size_t)(b * Ss + qg)) * Hh + h) * 64];
        float4 x = *(const float4*)&src[c4];
        float4 y = *(const float4*)&src[c4 + 32];
        float xa[4] = {x.x, x.y, x.z, x.w};
        float ya[4] = {y.x, y.y, y.z, y.w};
        float4 lo, hi;
        float* lop = &lo.x; float* hip = &hi.x;
#pragma unroll
        for (int j = 0; j < 4; j++) {
            float2 sc = T[qg * 32 + c4 + j];
            lop[j] = round_tf32(xa[j] * sc.y - ya[j] * sc.x);
            hip[j] = round_tf32(ya[j] * sc.y + xa[j] * sc.x);
        }
        *(float4*)&Qs[row * QSP + c4]      = lo;
        *(float4*)&Qs[row * QSP + c4 + 32] = hi;
    }
    // ---- K loader: 192 keys (jg = q0-128+key), rotated+rounded, d-major ----
#pragma unroll
    for (int pass = 0; pass < 6; pass++) {
        int id  = pass * 8 + warp;       // 0..47
        int kg  = id % 6;
        int c4  = (id / 6) * 4;
        int key = kg * 32 + lane;        // 0..191
        int jg  = q0 - 128 + key;
        float lov[4] = {0.f, 0.f, 0.f, 0.f};
        float hiv[4] = {0.f, 0.f, 0.f, 0.f};
        if (jg >= 0) {
            const float* src = &K[(((size_t)(b * Ss + jg)) * Hh + h) * 64];
            float4 x = *(const float4*)&src[c4];
            float4 y = *(const float4*)&src[c4 + 32];
            float xa[4] = {x.x, x.y, x.z, x.w};
            float ya[4] = {y.x, y.y, y.z, y.w};
#pragma unroll
            for (int j = 0; j < 4; j++) {
                float2 sc = T[jg * 32 + c4 + j];
                lov[j] = round_tf32(xa[j] * sc.y - ya[j] * sc.x);
                hiv[j] = round_tf32(ya[j] * sc.y + xa[j] * sc.x);
            }
        }
#pragma unroll
        for (int j = 0; j < 4; j++) {
            Kd[(c4 + j) * KDP + key]      = lov[j];
            Kd[(c4 + j + 32) * KDP + key] = hiv[j];
        }
    }
    __syncthreads();

    // ---- scores mma: warp tile 32q x 48key (2m x 4n warps), K=64 ----
    {
        const int wm = (warp >> 2) * 32;
        const int wn = (warp & 3) * 48;
        float acc[2][6][4];
#pragma unroll
        for (int mt = 0; mt < 2; mt++)
#pragma unroll
            for (int nt = 0; nt < 6; nt++)
#pragma unroll
                for (int j = 0; j < 4; j++) acc[mt][nt][j] = 0.0f;

#pragma unroll
        for (int kk = 0; kk < 8; kk++) {
            const int k8 = kk * 8;
            uint32_t a[2][4], bf[6][2];
#pragma unroll
            for (int mt = 0; mt < 2; mt++) {
                int r = wm + mt * 16 + group;
                a[mt][0] = __float_as_uint(Qs[r * QSP + k8 + tig]);
                a[mt][1] = __float_as_uint(Qs[(r + 8) * QSP + k8 + tig]);
                a[mt][2] = __float_as_uint(Qs[r * QSP + k8 + tig + 4]);
                a[mt][3] = __float_as_uint(Qs[(r + 8) * QSP + k8 + tig + 4]);
            }
#pragma unroll
            for (int nt = 0; nt < 6; nt++) {
                int col = wn + nt * 8 + group;
                bf[nt][0] = __float_as_uint(Kd[(k8 + tig) * KDP + col]);
                bf[nt][1] = __float_as_uint(Kd[(k8 + tig + 4) * KDP + col]);
            }
#pragma unroll
            for (int mt = 0; mt < 2; mt++)
#pragma unroll
                for (int nt = 0; nt < 6; nt++)
                    MMA_TF32(acc[mt][nt], a[mt], bf[nt]);
        }
        __syncthreads();   // all Kd reads done; Sc may now overwrite

        // masked/scaled epilogue -> Sc
#pragma unroll
        for (int mt = 0; mt < 2; mt++) {
#pragma unroll
            for (int nt = 0; nt < 6; nt++) {
                int col = wn + nt * 8 + tig * 2;
                int jgl = q0 - 128 + col;
#pragma unroll
                for (int hl = 0; hl < 2; hl++) {
                    int r  = wm + mt * 16 + group + hl * 8;
                    int qg = q0 + r;
                    bool ok0 = (jgl >= 0) && (jgl <= qg) && (jgl > qg - WIN);
                    bool ok1 = (jgl + 1 >= 0) && (jgl + 1 <= qg) && (jgl + 1 > qg - WIN);
                    float2 o;
                    o.x = ok0 ? acc[mt][nt][hl * 2 + 0] * 0.125f : -1e30f;
                    o.y = ok1 ? acc[mt][nt][hl * 2 + 1] * 0.125f : -1e30f;
                    *(float2*)&Sc[r * SCP + col] = o;
                }
            }
        }
    }
    __syncthreads();

    // ---- softmax: 4 threads per row, 48 cols each; store tf32-rounded p ----
    {
        int r = t >> 2;
        int p = t & 3;
        float mx = -1e30f;
        for (int jj = p * 48; jj < p * 48 + 48; jj++)
            mx = fmaxf(mx, Sc[r * SCP + jj]);
        mx = fmaxf(mx, __shfl_xor_sync(0xFFFFFFFFu, mx, 1));
        mx = fmaxf(mx, __shfl_xor_sync(0xFFFFFFFFu, mx, 2));
        float sum = 0.0f;
        for (int jj = p * 48; jj < p * 48 + 48; jj++) {
            float e = __expf(Sc[r * SCP + jj] - mx);
            Sc[r * SCP + jj] = e;
            sum += e;
        }
        sum += __shfl_xor_sync(0xFFFFFFFFu, sum, 1);
        sum += __shfl_xor_sync(0xFFFFFFFFu, sum, 2);
        float inv = 1.0f / sum;
        for (int jj = p * 48; jj < p * 48 + 48; jj++)
            Sc[r * SCP + jj] = round_tf32(Sc[r * SCP + jj] * inv);
    }

    // ---- PV mma: warp tile 32q x 16d (2m x 4n warps), K=192 in 3 chunks ----
    {
        const int wm = (warp >> 2) * 32;
        const int wn = (warp & 3) * 16;
        float acc[2][2][4];
#pragma unroll
        for (int mt = 0; mt < 2; mt++)
#pragma unroll
            for (int nt = 0; nt < 2; nt++)
#pragma unroll
                for (int j = 0; j < 4; j++) acc[mt][nt][j] = 0.0f;

        for (int c = 0; c < 3; c++) {
            __syncthreads();
            // V chunk loader: keys j0..j0+63 -> Vv[key][d] (rounded)
#pragma unroll
            for (int pass = 0; pass < 2; pass++) {
                int id  = pass * 8 + warp;
                int c4  = (id >> 1) * 4;
                int key = (id & 1) * 32 + lane;
                int jg  = q0 - 128 + c * 64 + key;
                float4 v0 = make_float4(0.f, 0.f, 0.f, 0.f);
                float4 v1 = make_float4(0.f, 0.f, 0.f, 0.f);
                if (jg >= 0) {
                    const float* src = &V[(((size_t)(b * Ss + jg)) * Hh + h) * 64];
                    v0 = *(const float4*)&src[c4];
                    v1 = *(const float4*)&src[c4 + 32];
                    v0.x = round_tf32(v0.x); v0.y = round_tf32(v0.y);
                    v0.z = round_tf32(v0.z); v0.w = round_tf32(v0.w);
                    v1.x = round_tf32(v1.x); v1.y = round_tf32(v1.y);
                    v1.z = round_tf32(v1.z); v1.w = round_tf32(v1.w);
                }
                *(float4*)&Vv[key * VPP + c4]      = v0;
                *(float4*)&Vv[key * VPP + c4 + 32] = v1;
            }
            __syncthreads();

#pragma unroll
            for (int kk = 0; kk < 8; kk++) {
                const int k8 = kk * 8;
                uint32_t a[2][4], bf[2][2];
#pragma unroll
                for (int mt = 0; mt < 2; mt++) {
                    int r = wm + mt * 16 + group;
                    int scol = c * 64 + k8 + tig;
                    a[mt][0] = __float_as_uint(Sc[r * SCP + scol]);
                    a[mt][1] = __float_as_uint(Sc[(r + 8) * SCP + scol]);
                    a[mt][2] = __float_as_uint(Sc[r * SCP + scol + 4]);
                    a[mt][3] = __float_as_uint(Sc[(r + 8) * SCP + scol + 4]);
                }
#pragma unroll
                for (int nt = 0; nt < 2; nt++) {
                    int dcol = wn + nt * 8 + group;
                    bf[nt][0] = __float_as_uint(Vv[(k8 + tig) * VPP + dcol]);
                    bf[nt][1] = __float_as_uint(Vv[(k8 + tig + 4) * VPP + dcol]);
                }
#pragma unroll
                for (int mt = 0; mt < 2; mt++)
#pragma unroll
                    for (int nt = 0; nt < 2; nt++)
                        MMA_TF32(acc[mt][nt], a[mt], bf[nt]);
            }
        }

        // epilogue -> Z (tf32-rounded for the WO GEMM)
#pragma unroll
        for (int mt = 0; mt < 2; mt++) {
#pragma unroll
            for (int nt = 0; nt < 2; nt++) {
                int col = wn + nt * 8 + tig * 2;
#pragma unroll
                for (int hl = 0; hl < 2; hl++) {
                    int r = wm + mt * 16 + group + hl * 8;
                    float2 o;
                    o.x = round_tf32(acc[mt][nt][hl * 2 + 0]);
                    o.y = round_tf32(acc[mt][nt][hl * 2 + 1]);
                    *(float2*)&Z[(((size_t)(b * Ss + q0 + r)) * Hh + h) * 64 + col] = o;
                }
            }
        }
    }
}

// ---------------------------------------------------------------------------
extern "C" void kernel_launch(void* const* d_in, const int* in_sizes, int n_in,
                              void* d_out, int out_size)
{
    const float* qin = (const float*)d_in[0];
    const float* kin = (const float*)d_in[1];
    const float* vin = (const float*)d_in[2];
    const float* WQ  = (const float*)d_in[3];
    const float* WK  = (const float*)d_in[4];
    const float* WV  = (const float*)d_in[5];
    const float* WO  = (const float*)d_in[6];
    const float* bQ  = (const float*)d_in[7];
    const float* bK  = (const float*)d_in[8];
    const float* bV  = (const float*)d_in[9];
    const float* bO  = (const float*)d_in[10];
    float* out = (float*)d_out;

    float *pQ, *pK, *pV, *pZ;
    float *pAq, *pAk, *pAv, *pWq, *pWk, *pWv, *pWo;
    float2* pT;
    cudaGetSymbolAddress((void**)&pQ, g_Q);
    cudaGetSymbolAddress((void**)&pK, g_K);
    cudaGetSymbolAddress((void**)&pV, g_V);
    cudaGetSymbolAddress((void**)&pZ, g_Z);
    cudaGetSymbolAddress((void**)&pAq, g_Aq);
    cudaGetSymbolAddress((void**)&pAk, g_Ak);
    cudaGetSymbolAddress((void**)&pAv, g_Av);
    cudaGetSymbolAddress((void**)&pWq, g_Wq);
    cudaGetSymbolAddress((void**)&pWk, g_Wk);
    cudaGetSymbolAddress((void**)&pWv, g_Wv);
    cudaGetSymbolAddress((void**)&pWo, g_Wo);
    cudaGetSymbolAddress((void**)&pT, g_T);

    const int M = Bb * Ss;       // 4096
    const int N = Hh * DHd;      // 768
    const int Kd = Dd;           // 768

    cudaFuncSetAttribute(tgemm_k<true>,
                         cudaFuncAttributeMaxDynamicSharedMemorySize, GEMM_SMEM);
    cudaFuncSetAttribute(tgemm_k<false>,
                         cudaFuncAttributeMaxDynamicSharedMemorySize, GEMM_SMEM);
    cudaFuncSetAttribute(attn_k,
                         cudaFuncAttributeMaxDynamicSharedMemorySize, ATTN_SMEM);

    // Pre-round GEMM operands + rotary table
    round3_k<<<dim3(3072, 3), 256>>>(qin, kin, vin, pAq, pAk, pAv);
    round4_k<<<dim3(576, 4), 256>>>(WQ, WK, WV, WO, pWq, pWk, pWv, pWo);
    table_k<<<Ss * 32 / 256, 256>>>(pT);

    // Fused QKV projections
    tgemm_k<true><<<dim3(N / 128, M / 128, 3), 256, GEMM_SMEM>>>(
        pAq, pAk, pAv, pWq, pWk, pWv, bQ, bK, bV, pQ, pK, pV, M, N, Kd);

    // Attention (rotary fused; scores+PV on tensor cores)
    attn_k<<<dim3(Ss / 64, Hh, Bb), 256, ATTN_SMEM>>>(pQ, pK, pV, pT, pZ);

    // Output projection
    tgemm_k<false><<<dim3(N / 128, M / 128, 1), 256, GEMM_SMEM>>>(
        pZ, pZ, pZ, pWo, pWo, pWo, bO, bO, bO, out, out, out, M, N, Kd);
}